// round 4
// baseline (speedup 1.0000x reference)
#include <cuda_runtime.h>
#include <cuda_bf16.h>
#include <cstdint>

// ============================================================================
// out[b,f] = -0.5 * sum_d ((x[b,d]-mu[f,d])/scale[f,d])^2
// One GEMM + bias:  out = A @ W^T + bias
//   A[b,:] = [ bf16(x^2) | bf16(x) ]             (8192 x 2048) bf16
//   W[f,:] = [ bf16(-0.5*inv2) | bf16(mu*inv2) ] (4096 x 2048) bf16
//   bias[f] = -0.5 * sum_d mu^2*inv2  (fp32 exact)
// R4 change: warp tile 32x64 -> 64x64 (4 warps/CTA, 2x2). LDSM smem traffic
// per K-stage drops 96KB -> 64KB; total smem demand 132 -> 100 B/cyc, under
// the 128 B/cyc crossbar cap, so the tensor pipe becomes the roofline.
// Keeps ST=3 / 110.6KB smem -> 2 CTAs/SM (R3 win).
// ============================================================================

#define B_DIM 8192
#define F_DIM 4096
#define K_DIM 2048

#define BM 128
#define BN 128
#define BK 64
#define ST 3
#define LDS_ROW 72                      // 64 bf16 + 8 pad
#define ROW_BYTES (LDS_ROW * 2)         // 144 B
#define TILE_BYTES (BM * ROW_BYTES)     // 18432
#define STAGE_BYTES (2 * TILE_BYTES)    // 36864
#define SMEM_DYN (ST * STAGE_BYTES)     // 110592 -> 2 CTAs/SM
#define KSTEPS (K_DIM / BK)             // 32

__device__ __align__(16) __nv_bfloat16 g_A[(size_t)B_DIM * K_DIM];  // 32 MB
__device__ __align__(16) __nv_bfloat16 g_W[(size_t)F_DIM * K_DIM];  // 16 MB
__device__ float g_bias[F_DIM];

// ---------------------------------------------------------------------------
__device__ __forceinline__ uint32_t smem_u32(const void* p) {
    uint32_t a;
    asm("{ .reg .u64 t; cvta.to.shared.u64 t, %1; cvt.u32.u64 %0, t; }"
        : "=r"(a) : "l"(p));
    return a;
}

__device__ __forceinline__ uint32_t pack_bf16(float a, float b) {
    uint32_t lo = (uint32_t)__bfloat16_as_ushort(__float2bfloat16(a));
    uint32_t hi = (uint32_t)__bfloat16_as_ushort(__float2bfloat16(b));
    return lo | (hi << 16);
}

#define CP_ASYNC16(dst, src) \
    asm volatile("cp.async.cg.shared.global [%0], [%1], 16;" \
                 :: "r"(dst), "l"(src) : "memory")
#define CP_COMMIT() asm volatile("cp.async.commit_group;" ::: "memory")
#define CP_WAIT1()  asm volatile("cp.async.wait_group 1;" ::: "memory")

#define LDSM_X4(r, addr) \
    asm volatile("ldmatrix.sync.aligned.m8n8.x4.shared.b16 {%0,%1,%2,%3}, [%4];" \
                 : "=r"((r)[0]), "=r"((r)[1]), "=r"((r)[2]), "=r"((r)[3]) \
                 : "r"(addr))

#define MMA_BF16(c, a, b0, b1) \
    asm volatile("mma.sync.aligned.m16n8k16.row.col.f32.bf16.bf16.f32 " \
                 "{%0,%1,%2,%3}, {%4,%5,%6,%7}, {%8,%9}, {%0,%1,%2,%3};" \
                 : "+f"((c)[0]), "+f"((c)[1]), "+f"((c)[2]), "+f"((c)[3]) \
                 : "r"((a)[0]), "r"((a)[1]), "r"((a)[2]), "r"((a)[3]), \
                   "r"(b0), "r"(b1))

// ---------------------------------------------------------------------------
// Prep 1: A = [ bf16(x^2) | bf16(x) ]
// ---------------------------------------------------------------------------
__global__ void prep_a_kernel(const float* __restrict__ x) {
    int b = blockIdx.x;
    int t = threadIdx.x;
    float4 v = reinterpret_cast<const float4*>(x)[b * 256 + t];
    uint2 sq = make_uint2(pack_bf16(v.x * v.x, v.y * v.y),
                          pack_bf16(v.z * v.z, v.w * v.w));
    uint2 vr = make_uint2(pack_bf16(v.x, v.y), pack_bf16(v.z, v.w));
    uint2* A2 = reinterpret_cast<uint2*>(g_A);
    A2[(size_t)b * 512 + t]       = sq;
    A2[(size_t)b * 512 + 256 + t] = vr;
}

// ---------------------------------------------------------------------------
// Prep 2: W = [ bf16(-0.5*inv2) | bf16(mu*inv2) ], bias
// ---------------------------------------------------------------------------
__global__ void prep_w_kernel(const float* __restrict__ mu,
                              const float* __restrict__ sd) {
    __shared__ float red[256];
    int f = blockIdx.x;
    int t = threadIdx.x;
    float4 m = reinterpret_cast<const float4*>(mu)[f * 256 + t];
    float4 s = reinterpret_cast<const float4*>(sd)[f * 256 + t];
    float4 i2 = make_float4(1.0f / (s.x * s.x), 1.0f / (s.y * s.y),
                            1.0f / (s.z * s.z), 1.0f / (s.w * s.w));
    uint2 w1 = make_uint2(pack_bf16(-0.5f * i2.x, -0.5f * i2.y),
                          pack_bf16(-0.5f * i2.z, -0.5f * i2.w));
    uint2 w2 = make_uint2(pack_bf16(m.x * i2.x, m.y * i2.y),
                          pack_bf16(m.z * i2.z, m.w * i2.w));
    uint2* W2 = reinterpret_cast<uint2*>(g_W);
    W2[(size_t)f * 512 + t]       = w1;
    W2[(size_t)f * 512 + 256 + t] = w2;
    red[t] = m.x * m.x * i2.x + m.y * m.y * i2.y +
             m.z * m.z * i2.z + m.w * m.w * i2.w;
    __syncthreads();
    #pragma unroll
    for (int o = 128; o > 0; o >>= 1) {
        if (t < o) red[t] += red[t + o];
        __syncthreads();
    }
    if (t == 0) g_bias[f] = -0.5f * red[0];
}

// ---------------------------------------------------------------------------
// GEMM: 128x128 tile, BK=64, 3-stage cp.async pipe, 2 CTAs/SM,
// 4 warps (2m x 2n), warp tile 64x64, mma.sync m16n8k16 bf16->fp32
// ---------------------------------------------------------------------------
__global__ void __launch_bounds__(128, 2)
gemm_kernel(float* __restrict__ out) {
    extern __shared__ char smem[];
    const uint32_t sbase = smem_u32(smem);

    const int tid  = threadIdx.x;
    const int lane = tid & 31;
    const int w    = tid >> 5;
    const int wm   = w & 1;          // 0..1 (M)
    const int wn   = w >> 1;         // 0..1 (N)

    const int bm = blockIdx.x & 63;
    const int bn = blockIdx.x >> 6;
    const int m0 = bm * BM;
    const int n0 = bn * BN;

    // cp.async: 128 threads x 16 chunks(16B) = two 128x64 bf16 tiles
    const int r0 = tid >> 3;         // 0..15 base row
    const int ch = tid & 7;          // 16B chunk in 128B row
    const __nv_bfloat16* srcA = g_A + (size_t)(m0 + r0) * K_DIM + ch * 8;
    const __nv_bfloat16* srcW = g_W + (size_t)(n0 + r0) * K_DIM + ch * 8;
    const uint32_t dstA0 = sbase + r0 * ROW_BYTES + ch * 16;
    const uint32_t dstW0 = dstA0 + TILE_BYTES;

    #define LOAD_STAGE(s, ks) do {                                          \
        uint32_t _da = dstA0 + (s) * STAGE_BYTES;                           \
        uint32_t _dw = dstW0 + (s) * STAGE_BYTES;                           \
        const __nv_bfloat16* _sa = srcA + (ks) * BK;                        \
        const __nv_bfloat16* _sw = srcW + (ks) * BK;                        \
        _Pragma("unroll")                                                   \
        for (int _i = 0; _i < 8; ++_i)                                      \
            CP_ASYNC16(_da + _i * 16 * ROW_BYTES, _sa + (size_t)_i * 16 * K_DIM); \
        _Pragma("unroll")                                                   \
        for (int _i = 0; _i < 8; ++_i)                                      \
            CP_ASYNC16(_dw + _i * 16 * ROW_BYTES, _sw + (size_t)_i * 16 * K_DIM); \
    } while (0)

    // ldmatrix addressing
    // A m16k16 frag: lanes 0-7 (m+l,k), 8-15 (m+8+l,k), 16-31 k+8 halves
    const uint32_t aAddr0 = sbase
        + (wm * 64 + (lane & 7) + ((lane >> 3) & 1) * 8) * ROW_BYTES
        + (lane >> 4) * 16;
    // B n16k16 frag: lanes 0-7 (n+l,k), 8-15 (n+l,k+8), 16-23 (n+8+l,k), ...
    const uint32_t bAddr0 = sbase + TILE_BYTES
        + (wn * 64 + (lane & 7) + ((lane >> 4) & 1) * 8) * ROW_BYTES
        + ((lane >> 3) & 1) * 16;

    float acc[4][8][4];
    #pragma unroll
    for (int i = 0; i < 4; ++i)
        #pragma unroll
        for (int j = 0; j < 8; ++j)
            #pragma unroll
            for (int q = 0; q < 4; ++q) acc[i][j][q] = 0.0f;

    // prologue: fill 2 stages
    LOAD_STAGE(0, 0);
    CP_COMMIT();
    LOAD_STAGE(1, 1);
    CP_COMMIT();

    int sc = 0;
    int sn = 2;
    for (int ks = 0; ks < KSTEPS; ++ks) {
        CP_WAIT1();
        __syncthreads();

        int nk = ks + 2;
        if (nk < KSTEPS) LOAD_STAGE(sn, nk);
        CP_COMMIT();
        sn = (sn == ST - 1) ? 0 : sn + 1;

        const uint32_t aA = aAddr0 + sc * STAGE_BYTES;
        const uint32_t bA = bAddr0 + sc * STAGE_BYTES;
        sc = (sc == ST - 1) ? 0 : sc + 1;

        #pragma unroll
        for (int kk = 0; kk < 4; ++kk) {
            uint32_t aF[4][4];                 // 4 m16 tiles
            #pragma unroll
            for (int im = 0; im < 4; ++im)
                LDSM_X4(aF[im], aA + im * 16 * ROW_BYTES + kk * 32);
            uint32_t bF[4][4];                 // 4 n16 tiles -> 8 n8 frags
            #pragma unroll
            for (int j = 0; j < 4; ++j)
                LDSM_X4(bF[j], bA + j * 16 * ROW_BYTES + kk * 32);
            #pragma unroll
            for (int im = 0; im < 4; ++im)
                #pragma unroll
                for (int in = 0; in < 8; ++in)
                    MMA_BF16(acc[im][in], aF[im],
                             bF[in >> 1][(in & 1) * 2],
                             bF[in >> 1][(in & 1) * 2 + 1]);
        }
    }

    // epilogue: fp32 + bias, float2 stores
    const int rowb = m0 + wm * 64 + (lane >> 2);
    const int colb = n0 + wn * 64 + (lane & 3) * 2;
    #pragma unroll
    for (int in = 0; in < 8; ++in) {
        const int col = colb + in * 8;
        const float2 bv = *reinterpret_cast<const float2*>(g_bias + col);
        #pragma unroll
        for (int im = 0; im < 4; ++im) {
            const int r = rowb + im * 16;
            float2 v0 = make_float2(acc[im][in][0] + bv.x, acc[im][in][1] + bv.y);
            float2 v1 = make_float2(acc[im][in][2] + bv.x, acc[im][in][3] + bv.y);
            *reinterpret_cast<float2*>(out + (size_t)r * F_DIM + col) = v0;
            *reinterpret_cast<float2*>(out + (size_t)(r + 8) * F_DIM + col) = v1;
        }
    }
}

// ---------------------------------------------------------------------------
extern "C" void kernel_launch(void* const* d_in, const int* in_sizes, int n_in,
                              void* d_out, int out_size) {
    (void)in_sizes; (void)n_in; (void)out_size;
    const float* x  = (const float*)d_in[0];
    const float* mu = (const float*)d_in[1];
    const float* sd = (const float*)d_in[2];
    float* out = (float*)d_out;

    prep_a_kernel<<<B_DIM, 256>>>(x);
    prep_w_kernel<<<F_DIM, 256>>>(mu, sd);

    static bool attr_set = false;
    if (!attr_set) {
        cudaFuncSetAttribute(gemm_kernel,
                             cudaFuncAttributeMaxDynamicSharedMemorySize, SMEM_DYN);
        attr_set = true;
    }
    gemm_kernel<<<(B_DIM / BM) * (BN == 128 ? F_DIM / BN : 0), 128, SMEM_DYN>>>(out);
}

// round 5
// speedup vs baseline: 1.0454x; 1.0454x over previous
#include <cuda_runtime.h>
#include <cuda_bf16.h>
#include <cstdint>

// ============================================================================
// out[b,f] = -0.5 * sum_d ((x[b,d]-mu[f,d])/scale[f,d])^2
// One GEMM + bias:  out = A @ W^T + bias
//   A[b,:] = [ bf16(x^2) | bf16(x) ]             (8192 x 2048) bf16
//   W[f,:] = [ bf16(-0.5*inv2) | bf16(mu*inv2) ] (4096 x 2048) bf16
//   bias[f] = -0.5 * sum_d mu^2*inv2  (fp32 exact)
// R5: GEMM mainloop reverted to the best-measured R3 config (8 warps 4x2,
// warp tile 32x64, BK=64, ST=3, 2 CTAs/SM — perf tracks warps/SM, not smem
// crossbar load). Prep kernels merged into ONE launch: saves a launch gap and
// shifts ncu's "-s 5 -c 1" onto the GEMM so the next round sees its profile.
// ============================================================================

#define B_DIM 8192
#define F_DIM 4096
#define K_DIM 2048

#define BM 128
#define BN 128
#define BK 64
#define ST 3
#define LDS_ROW 72                      // 64 bf16 + 8 pad
#define ROW_BYTES (LDS_ROW * 2)         // 144 B
#define TILE_BYTES (BM * ROW_BYTES)     // 18432
#define STAGE_BYTES (2 * TILE_BYTES)    // 36864
#define SMEM_DYN (ST * STAGE_BYTES)     // 110592 -> 2 CTAs/SM
#define KSTEPS (K_DIM / BK)             // 32

__device__ __align__(16) __nv_bfloat16 g_A[(size_t)B_DIM * K_DIM];  // 32 MB
__device__ __align__(16) __nv_bfloat16 g_W[(size_t)F_DIM * K_DIM];  // 16 MB
__device__ float g_bias[F_DIM];

// ---------------------------------------------------------------------------
__device__ __forceinline__ uint32_t smem_u32(const void* p) {
    uint32_t a;
    asm("{ .reg .u64 t; cvta.to.shared.u64 t, %1; cvt.u32.u64 %0, t; }"
        : "=r"(a) : "l"(p));
    return a;
}

__device__ __forceinline__ uint32_t pack_bf16(float a, float b) {
    uint32_t lo = (uint32_t)__bfloat16_as_ushort(__float2bfloat16(a));
    uint32_t hi = (uint32_t)__bfloat16_as_ushort(__float2bfloat16(b));
    return lo | (hi << 16);
}

#define CP_ASYNC16(dst, src) \
    asm volatile("cp.async.cg.shared.global [%0], [%1], 16;" \
                 :: "r"(dst), "l"(src) : "memory")
#define CP_COMMIT() asm volatile("cp.async.commit_group;" ::: "memory")
#define CP_WAIT1()  asm volatile("cp.async.wait_group 1;" ::: "memory")

#define LDSM_X4(r, addr) \
    asm volatile("ldmatrix.sync.aligned.m8n8.x4.shared.b16 {%0,%1,%2,%3}, [%4];" \
                 : "=r"((r)[0]), "=r"((r)[1]), "=r"((r)[2]), "=r"((r)[3]) \
                 : "r"(addr))

#define MMA_BF16(c, a, b0, b1) \
    asm volatile("mma.sync.aligned.m16n8k16.row.col.f32.bf16.bf16.f32 " \
                 "{%0,%1,%2,%3}, {%4,%5,%6,%7}, {%8,%9}, {%0,%1,%2,%3};" \
                 : "+f"((c)[0]), "+f"((c)[1]), "+f"((c)[2]), "+f"((c)[3]) \
                 : "r"((a)[0]), "r"((a)[1]), "r"((a)[2]), "r"((a)[3]), \
                   "r"(b0), "r"(b1))

// ---------------------------------------------------------------------------
// Merged prep: blocks [0, B_DIM) build A; blocks [B_DIM, B_DIM+F_DIM) build
// W and bias. One launch instead of two.
// ---------------------------------------------------------------------------
__global__ void prep_kernel(const float* __restrict__ x,
                            const float* __restrict__ mu,
                            const float* __restrict__ sd) {
    __shared__ float red[256];
    int bid = blockIdx.x;
    int t = threadIdx.x;

    if (bid < B_DIM) {
        // ---- A rows ----
        int b = bid;
        float4 v = reinterpret_cast<const float4*>(x)[b * 256 + t];
        uint2 sq = make_uint2(pack_bf16(v.x * v.x, v.y * v.y),
                              pack_bf16(v.z * v.z, v.w * v.w));
        uint2 vr = make_uint2(pack_bf16(v.x, v.y), pack_bf16(v.z, v.w));
        uint2* A2 = reinterpret_cast<uint2*>(g_A);
        A2[(size_t)b * 512 + t]       = sq;
        A2[(size_t)b * 512 + 256 + t] = vr;
    } else {
        // ---- W rows + bias ----
        int f = bid - B_DIM;
        float4 m = reinterpret_cast<const float4*>(mu)[f * 256 + t];
        float4 s = reinterpret_cast<const float4*>(sd)[f * 256 + t];
        float4 i2 = make_float4(1.0f / (s.x * s.x), 1.0f / (s.y * s.y),
                                1.0f / (s.z * s.z), 1.0f / (s.w * s.w));
        uint2 w1 = make_uint2(pack_bf16(-0.5f * i2.x, -0.5f * i2.y),
                              pack_bf16(-0.5f * i2.z, -0.5f * i2.w));
        uint2 w2 = make_uint2(pack_bf16(m.x * i2.x, m.y * i2.y),
                              pack_bf16(m.z * i2.z, m.w * i2.w));
        uint2* W2 = reinterpret_cast<uint2*>(g_W);
        W2[(size_t)f * 512 + t]       = w1;
        W2[(size_t)f * 512 + 256 + t] = w2;
        red[t] = m.x * m.x * i2.x + m.y * m.y * i2.y +
                 m.z * m.z * i2.z + m.w * m.w * i2.w;
        __syncthreads();
        #pragma unroll
        for (int o = 128; o > 0; o >>= 1) {
            if (t < o) red[t] += red[t + o];
            __syncthreads();
        }
        if (t == 0) g_bias[f] = -0.5f * red[0];
    }
}

// ---------------------------------------------------------------------------
// GEMM: 128x128 tile, BK=64, 3-stage cp.async pipe, 2 CTAs/SM,
// 8 warps (4m x 2n), warp tile 32x64, mma.sync m16n8k16 bf16->fp32
// (exact R3 configuration — best measured)
// ---------------------------------------------------------------------------
__global__ void __launch_bounds__(256, 2)
gemm_kernel(float* __restrict__ out) {
    extern __shared__ char smem[];
    const uint32_t sbase = smem_u32(smem);

    const int tid  = threadIdx.x;
    const int lane = tid & 31;
    const int w    = tid >> 5;
    const int wm   = w & 3;
    const int wn   = w >> 2;

    const int bm = blockIdx.x & 63;
    const int bn = blockIdx.x >> 6;
    const int m0 = bm * BM;
    const int n0 = bn * BN;

    const int r0 = tid >> 3;
    const int ch = tid & 7;
    const __nv_bfloat16* srcA = g_A + (size_t)(m0 + r0) * K_DIM + ch * 8;
    const __nv_bfloat16* srcW = g_W + (size_t)(n0 + r0) * K_DIM + ch * 8;
    const uint32_t dstA0 = sbase + r0 * ROW_BYTES + ch * 16;
    const uint32_t dstW0 = dstA0 + TILE_BYTES;

    #define LOAD_STAGE(s, ks) do {                                          \
        uint32_t _da = dstA0 + (s) * STAGE_BYTES;                           \
        uint32_t _dw = dstW0 + (s) * STAGE_BYTES;                           \
        const __nv_bfloat16* _sa = srcA + (ks) * BK;                        \
        const __nv_bfloat16* _sw = srcW + (ks) * BK;                        \
        _Pragma("unroll")                                                   \
        for (int _i = 0; _i < 4; ++_i)                                      \
            CP_ASYNC16(_da + _i * 32 * ROW_BYTES, _sa + (size_t)_i * 32 * K_DIM); \
        _Pragma("unroll")                                                   \
        for (int _i = 0; _i < 4; ++_i)                                      \
            CP_ASYNC16(_dw + _i * 32 * ROW_BYTES, _sw + (size_t)_i * 32 * K_DIM); \
    } while (0)

    const uint32_t aAddr0 = sbase
        + (wm * 32 + (lane & 7) + ((lane >> 3) & 1) * 8) * ROW_BYTES
        + (lane >> 4) * 16;
    const uint32_t bAddr0 = sbase + TILE_BYTES
        + (wn * 64 + (lane & 7) + ((lane >> 4) & 1) * 8) * ROW_BYTES
        + ((lane >> 3) & 1) * 16;

    float acc[2][8][4];
    #pragma unroll
    for (int i = 0; i < 2; ++i)
        #pragma unroll
        for (int j = 0; j < 8; ++j)
            #pragma unroll
            for (int q = 0; q < 4; ++q) acc[i][j][q] = 0.0f;

    LOAD_STAGE(0, 0);
    CP_COMMIT();
    LOAD_STAGE(1, 1);
    CP_COMMIT();

    int sc = 0;
    int sn = 2;
    for (int ks = 0; ks < KSTEPS; ++ks) {
        CP_WAIT1();
        __syncthreads();

        int nk = ks + 2;
        if (nk < KSTEPS) LOAD_STAGE(sn, nk);
        CP_COMMIT();
        sn = (sn == ST - 1) ? 0 : sn + 1;

        const uint32_t aA = aAddr0 + sc * STAGE_BYTES;
        const uint32_t bA = bAddr0 + sc * STAGE_BYTES;
        sc = (sc == ST - 1) ? 0 : sc + 1;

        #pragma unroll
        for (int kk = 0; kk < 4; ++kk) {
            uint32_t aF[2][4];
            #pragma unroll
            for (int im = 0; im < 2; ++im)
                LDSM_X4(aF[im], aA + im * 16 * ROW_BYTES + kk * 32);
            uint32_t bF[4][4];
            #pragma unroll
            for (int j = 0; j < 4; ++j)
                LDSM_X4(bF[j], bA + j * 16 * ROW_BYTES + kk * 32);
            #pragma unroll
            for (int im = 0; im < 2; ++im)
                #pragma unroll
                for (int in = 0; in < 8; ++in)
                    MMA_BF16(acc[im][in], aF[im],
                             bF[in >> 1][(in & 1) * 2],
                             bF[in >> 1][(in & 1) * 2 + 1]);
        }
    }

    const int rowb = m0 + wm * 32 + (lane >> 2);
    const int colb = n0 + wn * 64 + (lane & 3) * 2;
    #pragma unroll
    for (int in = 0; in < 8; ++in) {
        const int col = colb + in * 8;
        const float2 bv = *reinterpret_cast<const float2*>(g_bias + col);
        #pragma unroll
        for (int im = 0; im < 2; ++im) {
            const int r = rowb + im * 16;
            float2 v0 = make_float2(acc[im][in][0] + bv.x, acc[im][in][1] + bv.y);
            float2 v1 = make_float2(acc[im][in][2] + bv.x, acc[im][in][3] + bv.y);
            *reinterpret_cast<float2*>(out + (size_t)r * F_DIM + col) = v0;
            *reinterpret_cast<float2*>(out + (size_t)(r + 8) * F_DIM + col) = v1;
        }
    }
}

// ---------------------------------------------------------------------------
extern "C" void kernel_launch(void* const* d_in, const int* in_sizes, int n_in,
                              void* d_out, int out_size) {
    (void)in_sizes; (void)n_in; (void)out_size;
    const float* x  = (const float*)d_in[0];
    const float* mu = (const float*)d_in[1];
    const float* sd = (const float*)d_in[2];
    float* out = (float*)d_out;

    prep_kernel<<<B_DIM + F_DIM, 256>>>(x, mu, sd);

    static bool attr_set = false;
    if (!attr_set) {
        cudaFuncSetAttribute(gemm_kernel,
                             cudaFuncAttributeMaxDynamicSharedMemorySize, SMEM_DYN);
        attr_set = true;
    }
    gemm_kernel<<<(B_DIM / BM) * (F_DIM / BN), 256, SMEM_DYN>>>(out);
}

// round 6
// speedup vs baseline: 1.2968x; 1.2404x over previous
#include <cuda_runtime.h>
#include <cuda.h>
#include <cuda_bf16.h>
#include <cstdint>

// ============================================================================
// out[b,f] = -0.5 * sum_d ((x[b,d]-mu[f,d])/scale[f,d])^2
// One GEMM + bias:  out = A @ W^T + bias
//   A[b,:] = [ bf16(x^2) | bf16(x) ]             (8192 x 2048) bf16
//   W[f,:] = [ bf16(-0.5*inv2) | bf16(mu*inv2) ] (4096 x 2048) bf16
//   bias[f] = -0.5 * sum_d mu^2*inv2  (fp32 exact)
// R6: replace 2048 LDGSTS/stage with 2 TMA loads/stage (cp.async.bulk.tensor
// is base-sm_103 PTX; only tcgen05/multicast need 'a'). R5 profile showed LSU
// as loaded as the tensor pipe (both ~62%) from cp.async issue cost; TMA frees
// the LSU and the compute warps. SW128 swizzle replaces row padding
// (stage 36.9KB -> 32KB). Mainloop/warp layout = R5 exactly (best measured).
// ============================================================================

#define B_DIM 8192
#define F_DIM 4096
#define K_DIM 2048

#define BM 128
#define BN 128
#define BK 64
#define ST 3
#define A_TILE_BYTES 16384              // 128 rows x 128B (64 bf16)
#define STAGE_BYTES 32768               // A + W tiles
#define SMEM_DYN (1024 + ST * STAGE_BYTES)   // align slack + 3 stages = 99328
#define KSTEPS (K_DIM / BK)             // 32

__device__ __align__(16) __nv_bfloat16 g_A[(size_t)B_DIM * K_DIM];  // 32 MB
__device__ __align__(16) __nv_bfloat16 g_W[(size_t)F_DIM * K_DIM];  // 16 MB
__device__ float g_bias[F_DIM];

// ---------------------------------------------------------------------------
__device__ __forceinline__ uint32_t smem_u32(const void* p) {
    uint32_t a;
    asm("{ .reg .u64 t; cvta.to.shared.u64 t, %1; cvt.u32.u64 %0, t; }"
        : "=r"(a) : "l"(p));
    return a;
}

__device__ __forceinline__ uint32_t pack_bf16(float a, float b) {
    uint32_t lo = (uint32_t)__bfloat16_as_ushort(__float2bfloat16(a));
    uint32_t hi = (uint32_t)__bfloat16_as_ushort(__float2bfloat16(b));
    return lo | (hi << 16);
}

#define MBAR_INIT(addr, cnt) \
    asm volatile("mbarrier.init.shared.b64 [%0], %1;" :: "r"(addr), "r"(cnt) : "memory")

#define MBAR_EXPECT_TX(addr, bytes) \
    asm volatile("mbarrier.arrive.expect_tx.shared.b64 _, [%0], %1;" \
                 :: "r"(addr), "r"(bytes) : "memory")

__device__ __forceinline__ void mbar_wait(uint32_t mbar, uint32_t parity) {
    asm volatile(
        "{\n\t.reg .pred P;\n"
        "W_%=:\n\t"
        "mbarrier.try_wait.parity.shared::cta.b64 P, [%0], %1, 0x989680;\n\t"
        "@!P bra W_%=;\n\t"
        "}"
        :: "r"(mbar), "r"(parity) : "memory");
}

#define TMA_LOAD_3D(smem, map, cx, cy, cz, mbar) \
    asm volatile( \
        "cp.async.bulk.tensor.3d.shared::cta.global.tile.mbarrier::complete_tx::bytes " \
        "[%0], [%1, {%2, %3, %4}], [%5];" \
        :: "r"((uint32_t)(smem)), "l"(map), "r"((int32_t)(cx)), "r"((int32_t)(cy)), \
           "r"((int32_t)(cz)), "r"((uint32_t)(mbar)) : "memory")

#define FENCE_PROXY_ASYNC() \
    asm volatile("fence.proxy.async.shared::cta;" ::: "memory")

#define LDSM_X4(r, addr) \
    asm volatile("ldmatrix.sync.aligned.m8n8.x4.shared.b16 {%0,%1,%2,%3}, [%4];" \
                 : "=r"((r)[0]), "=r"((r)[1]), "=r"((r)[2]), "=r"((r)[3]) \
                 : "r"(addr))

#define MMA_BF16(c, a, b0, b1) \
    asm volatile("mma.sync.aligned.m16n8k16.row.col.f32.bf16.bf16.f32 " \
                 "{%0,%1,%2,%3}, {%4,%5,%6,%7}, {%8,%9}, {%0,%1,%2,%3};" \
                 : "+f"((c)[0]), "+f"((c)[1]), "+f"((c)[2]), "+f"((c)[3]) \
                 : "r"((a)[0]), "r"((a)[1]), "r"((a)[2]), "r"((a)[3]), \
                   "r"(b0), "r"(b1))

// ---------------------------------------------------------------------------
// Merged prep: blocks [0, B_DIM) build A; [B_DIM, B_DIM+F_DIM) build W + bias.
// ---------------------------------------------------------------------------
__global__ void prep_kernel(const float* __restrict__ x,
                            const float* __restrict__ mu,
                            const float* __restrict__ sd) {
    __shared__ float red[256];
    int bid = blockIdx.x;
    int t = threadIdx.x;

    if (bid < B_DIM) {
        int b = bid;
        float4 v = reinterpret_cast<const float4*>(x)[b * 256 + t];
        uint2 sq = make_uint2(pack_bf16(v.x * v.x, v.y * v.y),
                              pack_bf16(v.z * v.z, v.w * v.w));
        uint2 vr = make_uint2(pack_bf16(v.x, v.y), pack_bf16(v.z, v.w));
        uint2* A2 = reinterpret_cast<uint2*>(g_A);
        A2[(size_t)b * 512 + t]       = sq;
        A2[(size_t)b * 512 + 256 + t] = vr;
    } else {
        int f = bid - B_DIM;
        float4 m = reinterpret_cast<const float4*>(mu)[f * 256 + t];
        float4 s = reinterpret_cast<const float4*>(sd)[f * 256 + t];
        float4 i2 = make_float4(1.0f / (s.x * s.x), 1.0f / (s.y * s.y),
                                1.0f / (s.z * s.z), 1.0f / (s.w * s.w));
        uint2 w1 = make_uint2(pack_bf16(-0.5f * i2.x, -0.5f * i2.y),
                              pack_bf16(-0.5f * i2.z, -0.5f * i2.w));
        uint2 w2 = make_uint2(pack_bf16(m.x * i2.x, m.y * i2.y),
                              pack_bf16(m.z * i2.z, m.w * i2.w));
        uint2* W2 = reinterpret_cast<uint2*>(g_W);
        W2[(size_t)f * 512 + t]       = w1;
        W2[(size_t)f * 512 + 256 + t] = w2;
        red[t] = m.x * m.x * i2.x + m.y * m.y * i2.y +
                 m.z * m.z * i2.z + m.w * m.w * i2.w;
        __syncthreads();
        #pragma unroll
        for (int o = 128; o > 0; o >>= 1) {
            if (t < o) red[t] += red[t + o];
            __syncthreads();
        }
        if (t == 0) g_bias[f] = -0.5f * red[0];
    }
}

// ---------------------------------------------------------------------------
// GEMM: 128x128 tile, BK=64, 3-stage TMA pipe (SW128 swizzle), 2 CTAs/SM,
// 8 warps (4m x 2n), warp tile 32x64, mma.sync m16n8k16 bf16->fp32
// ---------------------------------------------------------------------------
__global__ void __launch_bounds__(256, 2)
gemm_kernel(const __grid_constant__ CUtensorMap tmA,
            const __grid_constant__ CUtensorMap tmW,
            float* __restrict__ out) {
    extern __shared__ char smem_raw[];
    const uint32_t STAGE0 = (smem_u32(smem_raw) + 1023u) & ~1023u;
    __shared__ __align__(8) uint64_t mb[ST];

    const int tid  = threadIdx.x;
    const int lane = tid & 31;
    const int w    = tid >> 5;
    const int wm   = w & 3;
    const int wn   = w >> 2;

    const int bm = blockIdx.x & 63;
    const int bn = blockIdx.x >> 6;
    const int m0 = bm * BM;
    const int n0 = bn * BN;

    // mbarrier init
    if (tid == 0) {
        #pragma unroll
        for (int s = 0; s < ST; ++s) MBAR_INIT(smem_u32(&mb[s]), 1);
        FENCE_PROXY_ASYNC();
    }
    __syncthreads();

    // prologue: stages 0 and 1
    if (tid == 0) {
        MBAR_EXPECT_TX(smem_u32(&mb[0]), (uint32_t)STAGE_BYTES);
        TMA_LOAD_3D(STAGE0,                 &tmA, 0,  m0, 0, smem_u32(&mb[0]));
        TMA_LOAD_3D(STAGE0 + A_TILE_BYTES,  &tmW, 0,  n0, 0, smem_u32(&mb[0]));
        MBAR_EXPECT_TX(smem_u32(&mb[1]), (uint32_t)STAGE_BYTES);
        TMA_LOAD_3D(STAGE0 + STAGE_BYTES,                &tmA, BK, m0, 0, smem_u32(&mb[1]));
        TMA_LOAD_3D(STAGE0 + STAGE_BYTES + A_TILE_BYTES, &tmW, BK, n0, 0, smem_u32(&mb[1]));
    }

    // ldmatrix addressing with SW128 XOR swizzle:
    // physical = rowbase*128 + ((chunk16 ^ (row&7)) << 4); row&7 == lane&7 here.
    const int sw = lane & 7;
    const uint32_t aRow0 = STAGE0
        + (uint32_t)(wm * 32 + (lane & 7) + ((lane >> 3) & 1) * 8) * 128u;
    const int cA0 = lane >> 4;                 // 16B-chunk low bit(s) for A
    const uint32_t bRow0 = STAGE0 + A_TILE_BYTES
        + (uint32_t)(wn * 64 + (lane & 7) + ((lane >> 4) & 1) * 8) * 128u;
    const int cB0 = (lane >> 3) & 1;

    float acc[2][8][4];
    #pragma unroll
    for (int i = 0; i < 2; ++i)
        #pragma unroll
        for (int j = 0; j < 8; ++j)
            #pragma unroll
            for (int q = 0; q < 4; ++q) acc[i][j][q] = 0.0f;

    int sc = 0, sn = 2;
    uint32_t ph = 0;
    for (int ks = 0; ks < KSTEPS; ++ks) {
        __syncthreads();                        // stage sn's previous readers done
        int nk = ks + 2;
        if (tid == 0 && nk < KSTEPS) {
            uint32_t mbn = smem_u32(&mb[sn]);
            uint32_t sa = STAGE0 + (uint32_t)sn * STAGE_BYTES;
            MBAR_EXPECT_TX(mbn, (uint32_t)STAGE_BYTES);
            TMA_LOAD_3D(sa,                &tmA, nk * BK, m0, 0, mbn);
            TMA_LOAD_3D(sa + A_TILE_BYTES, &tmW, nk * BK, n0, 0, mbn);
        }
        sn = (sn == ST - 1) ? 0 : sn + 1;

        mbar_wait(smem_u32(&mb[sc]), ph);
        const uint32_t sb = (uint32_t)sc * STAGE_BYTES;
        if (++sc == ST) { sc = 0; ph ^= 1; }

        #pragma unroll
        for (int kk = 0; kk < 4; ++kk) {
            const uint32_t aoff = (uint32_t)(((kk * 2 + cA0) ^ sw) << 4);
            const uint32_t boff = (uint32_t)(((kk * 2 + cB0) ^ sw) << 4);
            uint32_t aF[2][4];
            #pragma unroll
            for (int im = 0; im < 2; ++im)
                LDSM_X4(aF[im], aRow0 + sb + im * 2048 + aoff);
            uint32_t bF[4][4];
            #pragma unroll
            for (int j = 0; j < 4; ++j)
                LDSM_X4(bF[j], bRow0 + sb + j * 2048 + boff);
            #pragma unroll
            for (int im = 0; im < 2; ++im)
                #pragma unroll
                for (int in = 0; in < 8; ++in)
                    MMA_BF16(acc[im][in], aF[im],
                             bF[in >> 1][(in & 1) * 2],
                             bF[in >> 1][(in & 1) * 2 + 1]);
        }
    }

    // epilogue: fp32 + bias, float2 stores
    const int rowb = m0 + wm * 32 + (lane >> 2);
    const int colb = n0 + wn * 64 + (lane & 3) * 2;
    #pragma unroll
    for (int in = 0; in < 8; ++in) {
        const int col = colb + in * 8;
        const float2 bv = *reinterpret_cast<const float2*>(g_bias + col);
        #pragma unroll
        for (int im = 0; im < 2; ++im) {
            const int r = rowb + im * 16;
            float2 v0 = make_float2(acc[im][in][0] + bv.x, acc[im][in][1] + bv.y);
            float2 v1 = make_float2(acc[im][in][2] + bv.x, acc[im][in][3] + bv.y);
            *reinterpret_cast<float2*>(out + (size_t)r * F_DIM + col) = v0;
            *reinterpret_cast<float2*>(out + (size_t)(r + 8) * F_DIM + col) = v1;
        }
    }
}

// ---------------------------------------------------------------------------
typedef CUresult (*EncodeFn)(CUtensorMap*, CUtensorMapDataType, unsigned int,
                             void*, const unsigned long long*,
                             const unsigned long long*, const unsigned int*,
                             const unsigned int*, CUtensorMapInterleave,
                             CUtensorMapSwizzle, CUtensorMapL2promotion,
                             CUtensorMapFloatOOBfill);

static CUtensorMap s_tmA, s_tmW;
static bool s_init = false;

extern "C" void kernel_launch(void* const* d_in, const int* in_sizes, int n_in,
                              void* d_out, int out_size) {
    (void)in_sizes; (void)n_in; (void)out_size;
    const float* x  = (const float*)d_in[0];
    const float* mu = (const float*)d_in[1];
    const float* sd = (const float*)d_in[2];
    float* out = (float*)d_out;

    if (!s_init) {
        void* fn = nullptr;
        cudaDriverEntryPointQueryResult qr;
        cudaGetDriverEntryPointByVersion("cuTensorMapEncodeTiled", &fn, 12000,
                                         cudaEnableDefault, &qr);
        EncodeFn encode = (EncodeFn)fn;

        void *gA, *gW;
        cudaGetSymbolAddress(&gA, g_A);
        cudaGetSymbolAddress(&gW, g_W);

        {
            unsigned long long dims[3] = {K_DIM, B_DIM, 1};
            unsigned long long str[2]  = {(unsigned long long)K_DIM * 2,
                                          (unsigned long long)B_DIM * K_DIM * 2};
            unsigned int box[3] = {BK, BM, 1};   // 64 bf16 = 128B rows (SW128)
            unsigned int es[3]  = {1, 1, 1};
            encode(&s_tmA, CU_TENSOR_MAP_DATA_TYPE_BFLOAT16, 3, gA,
                   dims, str, box, es,
                   CU_TENSOR_MAP_INTERLEAVE_NONE, CU_TENSOR_MAP_SWIZZLE_128B,
                   CU_TENSOR_MAP_L2_PROMOTION_L2_128B,
                   CU_TENSOR_MAP_FLOAT_OOB_FILL_NONE);
        }
        {
            unsigned long long dims[3] = {K_DIM, F_DIM, 1};
            unsigned long long str[2]  = {(unsigned long long)K_DIM * 2,
                                          (unsigned long long)F_DIM * K_DIM * 2};
            unsigned int box[3] = {BK, BN, 1};
            unsigned int es[3]  = {1, 1, 1};
            encode(&s_tmW, CU_TENSOR_MAP_DATA_TYPE_BFLOAT16, 3, gW,
                   dims, str, box, es,
                   CU_TENSOR_MAP_INTERLEAVE_NONE, CU_TENSOR_MAP_SWIZZLE_128B,
                   CU_TENSOR_MAP_L2_PROMOTION_L2_128B,
                   CU_TENSOR_MAP_FLOAT_OOB_FILL_NONE);
        }
        cudaFuncSetAttribute(gemm_kernel,
                             cudaFuncAttributeMaxDynamicSharedMemorySize, SMEM_DYN);
        s_init = true;
    }

    prep_kernel<<<B_DIM + F_DIM, 256>>>(x, mu, sd);
    gemm_kernel<<<(B_DIM / BM) * (F_DIM / BN), 256, SMEM_DYN>>>(s_tmA, s_tmW, out);
}